// round 1
// baseline (speedup 1.0000x reference)
#include <cuda_runtime.h>
#include <math.h>

// Problem geometry
#define C_    80
#define H_    128
#define W_    256
#define HW_   32768          // H_*W_
#define CHW_  2621440        // C_*HW_
#define D_    256
#define P_    131072         // 256*512 embedding spatial
#define KTOP  50
#define NBINS 1024
#define CAP   65536
#define GEMM_BLOCKS 512      // P_ / 256 cols per block
#define OUT_SCORES 6553600   // KTOP * P_
#define OUT_CATS   6553650

// ---------------- scratch (static device globals; no allocation) -------------
__device__ float g_sig[CHW_];
__device__ float g_cent[CHW_];
__device__ float g_masked[CHW_];
__device__ int   g_hist[NBINS];
__device__ int   g_thresh_bin;
__device__ int   g_cand_cnt;
__device__ float g_cand_val[CAP];
__device__ int   g_cand_idx[CAP];
__device__ float g_scores[KTOP];
__device__ int   g_spatial[KTOP];
__device__ int   g_cats[KTOP];
__device__ float g_AT[D_ * KTOP];            // A^T: [d][k]
__device__ float g_psum[GEMM_BLOCKS * KTOP];
__device__ float g_pcnt[GEMM_BLOCKS * KTOP];

__device__ __forceinline__ float sigmoidf_(float x) {
    return 1.0f / (1.0f + expf(-x));
}

// packed f32x2 helpers (sm_100+)
__device__ __forceinline__ unsigned long long pk2(float x, float y) {
    unsigned long long r;
    asm("mov.b64 %0, {%1, %2};" : "=l"(r) : "f"(x), "f"(y));
    return r;
}
__device__ __forceinline__ unsigned long long fma2(unsigned long long a,
                                                   unsigned long long b,
                                                   unsigned long long c) {
    unsigned long long d;
    asm("fma.rn.f32x2 %0, %1, %2, %3;" : "=l"(d) : "l"(a), "l"(b), "l"(c));
    return d;
}
__device__ __forceinline__ void upk2(unsigned long long v, float& x, float& y) {
    asm("mov.b64 {%0, %1}, %2;" : "=f"(x), "=f"(y) : "l"(v));
}

// ---------------- 0: zero small state ---------------------------------------
__global__ void zero_kernel() {
    int t = threadIdx.x;
    if (t < NBINS) g_hist[t] = 0;
    if (t == 0) { g_cand_cnt = 0; g_thresh_bin = 1; }
}

// ---------------- 1: sigmoid -------------------------------------------------
__global__ void sig_kernel(const float* __restrict__ x) {
    int i = blockIdx.x * blockDim.x + threadIdx.x;   // float4 index
    if (i >= CHW_ / 4) return;
    float4 v = ((const float4*)x)[i];
    float4 o;
    o.x = sigmoidf_(v.x); o.y = sigmoidf_(v.y);
    o.z = sigmoidf_(v.z); o.w = sigmoidf_(v.w);
    ((float4*)g_sig)[i] = o;
}

// ---------------- 2: centers = 0.5*(sig + avg3(sig)) -------------------------
__global__ void cent_kernel() {
    int i = blockIdx.x * blockDim.x + threadIdx.x;
    if (i >= CHW_) return;
    int c   = i >> 15;          // / HW_
    int hw  = i & (HW_ - 1);
    int r   = hw >> 8;          // / W_
    int col = hw & (W_ - 1);
    const float* base = g_sig + c * HW_;
    float sum = 0.0f;
    #pragma unroll
    for (int dr = -1; dr <= 1; dr++) {
        int rr = r + dr;
        if (rr < 0 || rr >= H_) continue;
        #pragma unroll
        for (int dc = -1; dc <= 1; dc++) {
            int cc = col + dc;
            if (cc < 0 || cc >= W_) continue;
            sum += base[rr * W_ + cc];
        }
    }
    g_cent[i] = 0.5f * (g_sig[i] + sum * (1.0f / 9.0f));
}

// ---------------- 3: peak mask + histogram -----------------------------------
__global__ void peak_hist_kernel() {
    __shared__ int sh[NBINS];
    for (int j = threadIdx.x; j < NBINS; j += blockDim.x) sh[j] = 0;
    __syncthreads();

    int i = blockIdx.x * blockDim.x + threadIdx.x;
    if (i < CHW_) {
        int c   = i >> 15;
        int hw  = i & (HW_ - 1);
        int r   = hw >> 8;
        int col = hw & (W_ - 1);
        const float* base = g_cent + c * HW_;
        float m = -1e30f;
        #pragma unroll
        for (int dr = -1; dr <= 1; dr++) {
            int rr = r + dr;
            if (rr < 0 || rr >= H_) continue;
            #pragma unroll
            for (int dc = -1; dc <= 1; dc++) {
                int cc = col + dc;
                if (cc < 0 || cc >= W_) continue;
                float v = base[rr * W_ + cc];
                m = fmaxf(m, v);
            }
        }
        float cv = g_cent[i];
        float v = (m == cv) ? cv : 0.0f;
        g_masked[i] = v;
        int bin = (int)(v * (float)NBINS);
        bin = bin < 0 ? 0 : (bin > NBINS - 1 ? NBINS - 1 : bin);
        atomicAdd(&sh[bin], 1);
    }
    __syncthreads();
    for (int j = threadIdx.x; j < NBINS; j += blockDim.x)
        if (sh[j]) atomicAdd(&g_hist[j], sh[j]);
}

// ---------------- 4: threshold bin via suffix-sum ----------------------------
__global__ void thresh_kernel() {
    __shared__ int sh[NBINS];
    int t = threadIdx.x;
    sh[t] = g_hist[t];
    __syncthreads();
    for (int off = 1; off < NBINS; off <<= 1) {
        int v = sh[t] + ((t + off < NBINS) ? sh[t + off] : 0);
        __syncthreads();
        sh[t] = v;
        __syncthreads();
    }
    // sh[t] = count of values with bin >= t
    if (sh[t] >= KTOP && (t == NBINS - 1 || sh[t + 1] < KTOP))
        g_thresh_bin = t;
}

// ---------------- 5: collect candidates --------------------------------------
__global__ void collect_kernel() {
    int i = blockIdx.x * blockDim.x + threadIdx.x;
    if (i >= CHW_) return;
    float v = g_masked[i];
    int tb = g_thresh_bin;
    if (tb < 1) tb = 1;
    int bin = (int)(v * (float)NBINS);
    bin = bin < 0 ? 0 : (bin > NBINS - 1 ? NBINS - 1 : bin);
    if (bin >= tb && v > 0.0f) {
        int pos = atomicAdd(&g_cand_cnt, 1);
        if (pos < CAP) { g_cand_val[pos] = v; g_cand_idx[pos] = i; }
    }
}

// ---------------- 6: exact top-50 (tie: lower index first) -------------------
__global__ void select_kernel() {
    __shared__ float sv[256];
    __shared__ int sci[256];
    __shared__ int sj[256];
    int t = threadIdx.x;
    int n = g_cand_cnt;
    if (n > CAP) n = CAP;

    for (int it = 0; it < KTOP; it++) {
        float bv = -1e30f; int bci = 0x7fffffff; int bj = -1;
        for (int j = t; j < n; j += 256) {
            float v = g_cand_val[j];
            if (v > -0.5f) {
                int ci = g_cand_idx[j];
                if (v > bv || (v == bv && ci < bci)) { bv = v; bci = ci; bj = j; }
            }
        }
        sv[t] = bv; sci[t] = bci; sj[t] = bj;
        __syncthreads();
        for (int s = 128; s > 0; s >>= 1) {
            if (t < s) {
                if (sv[t + s] > sv[t] || (sv[t + s] == sv[t] && sci[t + s] < sci[t])) {
                    sv[t] = sv[t + s]; sci[t] = sci[t + s]; sj[t] = sj[t + s];
                }
            }
            __syncthreads();
        }
        if (t == 0) {
            if (sv[0] > -0.5f && sj[0] >= 0) {
                g_scores[it]  = sv[0];
                g_cats[it]    = sci[0] / HW_;
                g_spatial[it] = sci[0] % HW_;
                g_cand_val[sj[0]] = -1.0f;
            } else {
                g_scores[it] = 0.0f; g_cats[it] = 0; g_spatial[it] = 0;
            }
        }
        __syncthreads();
    }
}

// ---------------- 7: gather kernels A^T[d][k] --------------------------------
__global__ void gather_kernel(const float* __restrict__ ks) {
    int d = threadIdx.x;
    if (d >= D_) return;
    const float* row = ks + d * HW_;
    #pragma unroll 5
    for (int k = 0; k < KTOP; k++)
        g_AT[d * KTOP + k] = row[g_spatial[k]];
}

// ---------------- 8: GEMM [50,256]x[256,131072] + sigmoid + rescore ---------
// 512 blocks x 128 threads, 2 columns/thread, k packed in f32x2 pairs.
__global__ void __launch_bounds__(128) gemm_kernel(const float* __restrict__ emb,
                                                   float* __restrict__ out) {
    extern __shared__ float smem[];
    float* As   = smem;              // 12800 floats: [d][k]
    float* redS = smem + 12800;      // [4][50]
    float* redC = redS + 200;        // [4][50]

    int tid = threadIdx.x;
    // load A^T into shared
    for (int i = tid; i < D_ * KTOP; i += 128) As[i] = g_AT[i];
    __syncthreads();

    const unsigned long long* As64 = (const unsigned long long*)As; // [d][kk], 25 per d

    int c0 = blockIdx.x * 256 + tid * 2;
    const float2* ep = (const float2*)(emb + c0);   // stride per d: P_/2 float2

    unsigned long long acc0[25], acc1[25];
    #pragma unroll
    for (int kk = 0; kk < 25; kk++) { acc0[kk] = 0ull; acc1[kk] = 0ull; }

    float2 eb[4];
    #pragma unroll
    for (int j = 0; j < 4; j++) eb[j] = ep[j * (P_ / 2)];

    for (int d0 = 0; d0 < D_; d0 += 4) {
        float2 nb[4];
        #pragma unroll
        for (int j = 0; j < 4; j++) {
            int dn = d0 + 4 + j;
            if (dn > D_ - 1) dn = D_ - 1;
            nb[j] = ep[dn * (P_ / 2)];
        }
        #pragma unroll
        for (int j = 0; j < 4; j++) {
            int d = d0 + j;
            unsigned long long e0 = pk2(eb[j].x, eb[j].x);
            unsigned long long e1 = pk2(eb[j].y, eb[j].y);
            const unsigned long long* a = As64 + d * 25;
            #pragma unroll
            for (int kk = 0; kk < 25; kk++) {
                unsigned long long av = a[kk];
                acc0[kk] = fma2(av, e0, acc0[kk]);
                acc1[kk] = fma2(av, e1, acc1[kk]);
            }
        }
        #pragma unroll
        for (int j = 0; j < 4; j++) eb[j] = nb[j];
    }

    // epilogue: sigmoid, store masks, warp-reduce rescore partials
    int lane = tid & 31, warp = tid >> 5;
    #pragma unroll
    for (int kk = 0; kk < 25; kk++) {
        float a, b, c, d;
        upk2(acc0[kk], a, c);   // a: k=2kk col0, c: k=2kk+1 col0
        upk2(acc1[kk], b, d);   // b: k=2kk col1, d: k=2kk+1 col1

        // row 2kk
        {
            float m0 = sigmoidf_(a), m1 = sigmoidf_(b);
            float2 st; st.x = m0; st.y = m1;
            *(float2*)(out + (2 * kk) * P_ + c0) = st;
            float s  = (m0 > 0.4f ? m0 : 0.0f) + (m1 > 0.4f ? m1 : 0.0f);
            float cn = (m0 > 0.4f ? 1.0f : 0.0f) + (m1 > 0.4f ? 1.0f : 0.0f);
            #pragma unroll
            for (int o = 16; o > 0; o >>= 1) {
                s  += __shfl_down_sync(0xffffffffu, s,  o);
                cn += __shfl_down_sync(0xffffffffu, cn, o);
            }
            if (lane == 0) { redS[warp * KTOP + 2 * kk] = s; redC[warp * KTOP + 2 * kk] = cn; }
        }
        // row 2kk+1
        {
            float m0 = sigmoidf_(c), m1 = sigmoidf_(d);
            float2 st; st.x = m0; st.y = m1;
            *(float2*)(out + (2 * kk + 1) * P_ + c0) = st;
            float s  = (m0 > 0.4f ? m0 : 0.0f) + (m1 > 0.4f ? m1 : 0.0f);
            float cn = (m0 > 0.4f ? 1.0f : 0.0f) + (m1 > 0.4f ? 1.0f : 0.0f);
            #pragma unroll
            for (int o = 16; o > 0; o >>= 1) {
                s  += __shfl_down_sync(0xffffffffu, s,  o);
                cn += __shfl_down_sync(0xffffffffu, cn, o);
            }
            if (lane == 0) { redS[warp * KTOP + 2 * kk + 1] = s; redC[warp * KTOP + 2 * kk + 1] = cn; }
        }
    }
    __syncthreads();
    if (tid < KTOP) {
        float s  = redS[tid] + redS[KTOP + tid] + redS[2 * KTOP + tid] + redS[3 * KTOP + tid];
        float cn = redC[tid] + redC[KTOP + tid] + redC[2 * KTOP + tid] + redC[3 * KTOP + tid];
        g_psum[blockIdx.x * KTOP + tid] = s;
        g_pcnt[blockIdx.x * KTOP + tid] = cn;
    }
}

// ---------------- 9: final scores/cats ---------------------------------------
__global__ void final_kernel(float* __restrict__ out) {
    int k = threadIdx.x;
    if (k >= KTOP) return;
    float s = 0.0f, cn = 0.0f;
    for (int b = 0; b < GEMM_BLOCKS; b++) {
        s  += g_psum[b * KTOP + k];
        cn += g_pcnt[b * KTOP + k];
    }
    float factor = s / fmaxf(cn, 1e-8f);
    float sc = g_scores[k];
    float valid = (sc > 0.1f) ? 1.0f : 0.0f;
    out[OUT_SCORES + k] = sc * factor * valid;
    out[OUT_CATS + k]   = (float)g_cats[k];
}

// ---------------- launch -----------------------------------------------------
extern "C" void kernel_launch(void* const* d_in, const int* in_sizes, int n_in,
                              void* d_out, int out_size) {
    const float* thing_map    = (const float*)d_in[0];
    const float* kernel_space = (const float*)d_in[1];
    const float* embeddings   = (const float*)d_in[2];
    float* out = (float*)d_out;

    static bool attr_set = false;
    if (!attr_set) {
        cudaFuncSetAttribute(gemm_kernel,
                             cudaFuncAttributeMaxDynamicSharedMemorySize, 53248);
        attr_set = true;
    }

    zero_kernel<<<1, 1024>>>();
    sig_kernel<<<(CHW_ / 4 + 255) / 256, 256>>>(thing_map);
    cent_kernel<<<(CHW_ + 255) / 256, 256>>>();
    peak_hist_kernel<<<(CHW_ + 255) / 256, 256>>>();
    thresh_kernel<<<1, NBINS>>>();
    collect_kernel<<<(CHW_ + 255) / 256, 256>>>();
    select_kernel<<<1, 256>>>();
    gather_kernel<<<1, 256>>>(kernel_space);
    gemm_kernel<<<GEMM_BLOCKS, 128, (12800 + 400) * 4>>>(embeddings, out);
    final_kernel<<<1, 64>>>(out);
}

// round 2
// speedup vs baseline: 1.2437x; 1.2437x over previous
#include <cuda_runtime.h>
#include <math.h>

// Problem geometry
#define C_    80
#define H_    128
#define W_    256
#define HW_   32768          // H_*W_
#define CHW_  2621440        // C_*HW_
#define D_    256
#define P_    131072         // 256*512 embedding spatial
#define KTOP  50
#define NBINS 2048
#define CAP   65536
#define GEMM_BLOCKS 512      // P_ / 256 cols per block
#define OUT_SCORES 6553600   // KTOP * P_
#define OUT_CATS   6553650

// ---------------- scratch (static device globals; no allocation) -------------
__device__ float g_masked[CHW_];
__device__ int   g_hist[NBINS];      // zero-init at load; self-zeroed per replay
__device__ int   g_thresh_bin;
__device__ int   g_cand_cnt;         // reset by select_kernel each replay
__device__ float g_cand_val[CAP];
__device__ int   g_cand_idx[CAP];
__device__ float g_scores[KTOP];
__device__ int   g_spatial[KTOP];
__device__ int   g_cats[KTOP];
__device__ float g_AT[D_ * KTOP];            // A^T: [d][k]
__device__ float g_psum[GEMM_BLOCKS * KTOP];
__device__ float g_pcnt[GEMM_BLOCKS * KTOP];

__device__ __forceinline__ float fast_sigmoid(float x) {
    return 1.0f / (1.0f + __expf(-x));
}

// packed f32x2 helpers (sm_100+)
__device__ __forceinline__ unsigned long long pk2(float x, float y) {
    unsigned long long r;
    asm("mov.b64 %0, {%1, %2};" : "=l"(r) : "f"(x), "f"(y));
    return r;
}
__device__ __forceinline__ unsigned long long fma2(unsigned long long a,
                                                   unsigned long long b,
                                                   unsigned long long c) {
    unsigned long long d;
    asm("fma.rn.f32x2 %0, %1, %2, %3;" : "=l"(d) : "l"(a), "l"(b), "l"(c));
    return d;
}
__device__ __forceinline__ void upk2(unsigned long long v, float& x, float& y) {
    asm("mov.b64 {%0, %1}, %2;" : "=f"(x), "=f"(y) : "l"(v));
}

// ---------------- 1: fused sigmoid + avg3 + max3 + peak mask + histogram -----
// grid (8, 80): blockIdx.y = class, blockIdx.x = row-block of 16 rows.
// Tiles: sig rows [r0-2, r0+18) with 1-col halo; cent rows [r0-1, r0+17).
#define SW 260
__global__ void __launch_bounds__(256) fused_detect(const float* __restrict__ x) {
    __shared__ float s_sig[20 * SW];
    __shared__ float s_cent[18 * SW];
    __shared__ int   s_hist[NBINS];

    int c   = blockIdx.y;
    int r0  = blockIdx.x * 16;
    int tid = threadIdx.x;

    for (int i = tid; i < NBINS; i += 256) s_hist[i] = 0;

    const float* base = x + c * HW_;

    // phase 1: sigmoid into smem (zero padding outside image)
    for (int i = tid; i < 20 * 256; i += 256) {
        int row = i >> 8;
        int col = i & 255;
        int gr  = r0 - 2 + row;
        float v = 0.0f;
        if (gr >= 0 && gr < H_) v = fast_sigmoid(base[gr * W_ + col]);
        s_sig[row * SW + col + 1] = v;
        if (col == 0)   s_sig[row * SW + 0]   = 0.0f;
        if (col == 255) s_sig[row * SW + 257] = 0.0f;
    }
    __syncthreads();

    // phase 2: centers = 0.5*(sig + avg3x3(sig)) for rows [r0-1, r0+17)
    for (int i = tid; i < 18 * 256; i += 256) {
        int rj  = i >> 8;
        int col = i & 255;
        int gr  = r0 - 1 + rj;
        float v = 0.0f;
        if (gr >= 0 && gr < H_) {
            float sum = 0.0f;
            #pragma unroll
            for (int dr = 0; dr < 3; dr++) {
                const float* p = s_sig + (rj + dr) * SW + col;
                sum += p[0] + p[1] + p[2];
            }
            float center = s_sig[(rj + 1) * SW + col + 1];
            v = 0.5f * (center + sum * (1.0f / 9.0f));
        }
        s_cent[rj * SW + col + 1] = v;
        if (col == 0)   s_cent[rj * SW + 0]   = 0.0f;
        if (col == 255) s_cent[rj * SW + 257] = 0.0f;
    }
    __syncthreads();

    // phase 3: 3x3 max, peak mask, masked value out + histogram
    for (int i = tid; i < 16 * 256; i += 256) {
        int ri  = i >> 8;
        int col = i & 255;
        float m = 0.0f;
        #pragma unroll
        for (int dr = 0; dr < 3; dr++) {
            const float* p = s_cent + (ri + dr) * SW + col;
            m = fmaxf(m, fmaxf(p[0], fmaxf(p[1], p[2])));
        }
        float cv = s_cent[(ri + 1) * SW + col + 1];
        float v  = (m == cv) ? cv : 0.0f;
        g_masked[c * HW_ + (r0 + ri) * W_ + col] = v;
        int bin = (int)(v * (float)NBINS);
        bin = bin < 0 ? 0 : (bin > NBINS - 1 ? NBINS - 1 : bin);
        atomicAdd(&s_hist[bin], 1);
    }
    __syncthreads();
    for (int i = tid; i < NBINS; i += 256)
        if (s_hist[i]) atomicAdd(&g_hist[i], s_hist[i]);
}

// ---------------- 2: threshold bin via suffix-sum; self-zero hist ------------
__global__ void thresh_kernel() {
    __shared__ int a[NBINS], b[NBINS];
    int t = threadIdx.x;   // 1024
    for (int i = t; i < NBINS; i += 1024) a[i] = g_hist[i];
    __syncthreads();
    int* src = a; int* dst = b;
    for (int off = 1; off < NBINS; off <<= 1) {
        for (int i = t; i < NBINS; i += 1024)
            dst[i] = src[i] + ((i + off < NBINS) ? src[i + off] : 0);
        __syncthreads();
        int* tmp = src; src = dst; dst = tmp;
    }
    // src[t] = count of values with bin >= t
    for (int i = t; i < NBINS; i += 1024) {
        if (i >= 1 && src[i] >= KTOP && (i == NBINS - 1 || src[i + 1] < KTOP))
            g_thresh_bin = i;
    }
    if (t == 0 && src[1] < KTOP) g_thresh_bin = 1;
    // zero global histogram for the next replay
    for (int i = t; i < NBINS; i += 1024) g_hist[i] = 0;
}

// ---------------- 3: collect candidates --------------------------------------
__global__ void collect_kernel() {
    int i = blockIdx.x * blockDim.x + threadIdx.x;
    if (i >= CHW_) return;
    float v = g_masked[i];
    int tb = g_thresh_bin;
    if (tb < 1) tb = 1;
    int bin = (int)(v * (float)NBINS);
    bin = bin < 0 ? 0 : (bin > NBINS - 1 ? NBINS - 1 : bin);
    if (bin >= tb && v > 0.0f) {
        int pos = atomicAdd(&g_cand_cnt, 1);
        if (pos < CAP) { g_cand_val[pos] = v; g_cand_idx[pos] = i; }
    }
}

// ---------------- 4: exact top-50 (tie: lower index first); reset counter ----
__global__ void select_kernel() {
    __shared__ float sv[256];
    __shared__ int sci[256];
    __shared__ int sj[256];
    int t = threadIdx.x;
    int n = g_cand_cnt;
    if (n > CAP) n = CAP;

    for (int it = 0; it < KTOP; it++) {
        float bv = -1e30f; int bci = 0x7fffffff; int bj = -1;
        for (int j = t; j < n; j += 256) {
            float v = g_cand_val[j];
            if (v > -0.5f) {
                int ci = g_cand_idx[j];
                if (v > bv || (v == bv && ci < bci)) { bv = v; bci = ci; bj = j; }
            }
        }
        sv[t] = bv; sci[t] = bci; sj[t] = bj;
        __syncthreads();
        for (int s = 128; s > 0; s >>= 1) {
            if (t < s) {
                if (sv[t + s] > sv[t] || (sv[t + s] == sv[t] && sci[t + s] < sci[t])) {
                    sv[t] = sv[t + s]; sci[t] = sci[t + s]; sj[t] = sj[t + s];
                }
            }
            __syncthreads();
        }
        if (t == 0) {
            if (sv[0] > -0.5f && sj[0] >= 0) {
                g_scores[it]  = sv[0];
                g_cats[it]    = sci[0] / HW_;
                g_spatial[it] = sci[0] % HW_;
                g_cand_val[sj[0]] = -1.0f;
            } else {
                g_scores[it] = 0.0f; g_cats[it] = 0; g_spatial[it] = 0;
            }
        }
        __syncthreads();
    }
    if (t == 0) g_cand_cnt = 0;   // reset for next replay
}

// ---------------- 5: gather kernels A^T[d][k] (one block per k) --------------
__global__ void gather_kernel(const float* __restrict__ ks) {
    int k  = blockIdx.x;
    int sp = g_spatial[k];
    for (int d = threadIdx.x; d < D_; d += 256)
        g_AT[d * KTOP + k] = ks[d * HW_ + sp];
}

// ---------------- 6: GEMM [50,256]x[256,131072] + sigmoid + rescore ---------
// 512 blocks x 128 threads, 2 columns/thread, k packed in f32x2 pairs.
__global__ void __launch_bounds__(128) gemm_kernel(const float* __restrict__ emb,
                                                   float* __restrict__ out) {
    extern __shared__ float smem[];
    float* As   = smem;              // 12800 floats: [d][k]
    float* redS = smem + 12800;      // [4][50]
    float* redC = redS + 200;        // [4][50]

    int tid = threadIdx.x;
    for (int i = tid; i < D_ * KTOP; i += 128) As[i] = g_AT[i];
    __syncthreads();

    const unsigned long long* As64 = (const unsigned long long*)As; // [d][kk]

    int c0 = blockIdx.x * 256 + tid * 2;
    const float2* ep = (const float2*)(emb + c0);   // stride per d: P_/2 float2

    unsigned long long acc0[25], acc1[25];
    #pragma unroll
    for (int kk = 0; kk < 25; kk++) { acc0[kk] = 0ull; acc1[kk] = 0ull; }

    float2 eb[4];
    #pragma unroll
    for (int j = 0; j < 4; j++) eb[j] = __ldg(&ep[j * (P_ / 2)]);

    for (int d0 = 0; d0 < D_; d0 += 4) {
        float2 nb[4];
        #pragma unroll
        for (int j = 0; j < 4; j++) {
            int dn = d0 + 4 + j;
            if (dn > D_ - 1) dn = D_ - 1;
            nb[j] = __ldg(&ep[dn * (P_ / 2)]);
        }
        #pragma unroll
        for (int j = 0; j < 4; j++) {
            int d = d0 + j;
            unsigned long long e0 = pk2(eb[j].x, eb[j].x);
            unsigned long long e1 = pk2(eb[j].y, eb[j].y);
            const unsigned long long* a = As64 + d * 25;
            #pragma unroll
            for (int kk = 0; kk < 25; kk++) {
                unsigned long long av = a[kk];
                acc0[kk] = fma2(av, e0, acc0[kk]);
                acc1[kk] = fma2(av, e1, acc1[kk]);
            }
        }
        #pragma unroll
        for (int j = 0; j < 4; j++) eb[j] = nb[j];
    }

    // epilogue: sigmoid, store masks, warp-reduce rescore partials
    int lane = tid & 31, warp = tid >> 5;
    #pragma unroll
    for (int kk = 0; kk < 25; kk++) {
        float a, b, c, d;
        upk2(acc0[kk], a, c);   // a: k=2kk col0, c: k=2kk+1 col0
        upk2(acc1[kk], b, d);   // b: k=2kk col1, d: k=2kk+1 col1

        {
            float m0 = fast_sigmoid(a), m1 = fast_sigmoid(b);
            float2 st; st.x = m0; st.y = m1;
            *(float2*)(out + (2 * kk) * P_ + c0) = st;
            float s  = (m0 > 0.4f ? m0 : 0.0f) + (m1 > 0.4f ? m1 : 0.0f);
            float cn = (m0 > 0.4f ? 1.0f : 0.0f) + (m1 > 0.4f ? 1.0f : 0.0f);
            #pragma unroll
            for (int o = 16; o > 0; o >>= 1) {
                s  += __shfl_down_sync(0xffffffffu, s,  o);
                cn += __shfl_down_sync(0xffffffffu, cn, o);
            }
            if (lane == 0) { redS[warp * KTOP + 2 * kk] = s; redC[warp * KTOP + 2 * kk] = cn; }
        }
        {
            float m0 = fast_sigmoid(c), m1 = fast_sigmoid(d);
            float2 st; st.x = m0; st.y = m1;
            *(float2*)(out + (2 * kk + 1) * P_ + c0) = st;
            float s  = (m0 > 0.4f ? m0 : 0.0f) + (m1 > 0.4f ? m1 : 0.0f);
            float cn = (m0 > 0.4f ? 1.0f : 0.0f) + (m1 > 0.4f ? 1.0f : 0.0f);
            #pragma unroll
            for (int o = 16; o > 0; o >>= 1) {
                s  += __shfl_down_sync(0xffffffffu, s,  o);
                cn += __shfl_down_sync(0xffffffffu, cn, o);
            }
            if (lane == 0) { redS[warp * KTOP + 2 * kk + 1] = s; redC[warp * KTOP + 2 * kk + 1] = cn; }
        }
    }
    __syncthreads();
    if (tid < KTOP) {
        float s  = redS[tid] + redS[KTOP + tid] + redS[2 * KTOP + tid] + redS[3 * KTOP + tid];
        float cn = redC[tid] + redC[KTOP + tid] + redC[2 * KTOP + tid] + redC[3 * KTOP + tid];
        g_psum[blockIdx.x * KTOP + tid] = s;
        g_pcnt[blockIdx.x * KTOP + tid] = cn;
    }
}

// ---------------- 7: final scores/cats ---------------------------------------
__global__ void final_kernel(float* __restrict__ out) {
    int k = threadIdx.x;
    if (k >= KTOP) return;
    float s = 0.0f, cn = 0.0f;
    for (int b = 0; b < GEMM_BLOCKS; b++) {
        s  += g_psum[b * KTOP + k];
        cn += g_pcnt[b * KTOP + k];
    }
    float factor = s / fmaxf(cn, 1e-8f);
    float sc = g_scores[k];
    float valid = (sc > 0.1f) ? 1.0f : 0.0f;
    out[OUT_SCORES + k] = sc * factor * valid;
    out[OUT_CATS + k]   = (float)g_cats[k];
}

// ---------------- launch -----------------------------------------------------
extern "C" void kernel_launch(void* const* d_in, const int* in_sizes, int n_in,
                              void* d_out, int out_size) {
    const float* thing_map    = (const float*)d_in[0];
    const float* kernel_space = (const float*)d_in[1];
    const float* embeddings   = (const float*)d_in[2];
    float* out = (float*)d_out;

    static bool attr_set = false;
    if (!attr_set) {
        cudaFuncSetAttribute(gemm_kernel,
                             cudaFuncAttributeMaxDynamicSharedMemorySize, 53248);
        attr_set = true;
    }

    fused_detect<<<dim3(8, 80), 256>>>(thing_map);          // 1
    thresh_kernel<<<1, 1024>>>();                           // 2
    collect_kernel<<<(CHW_ + 255) / 256, 256>>>();          // 3
    select_kernel<<<1, 256>>>();                            // 4
    gather_kernel<<<KTOP, 256>>>(kernel_space);             // 5
    gemm_kernel<<<GEMM_BLOCKS, 128, 53248>>>(embeddings, out); // 6 (ncu -s 5 lands here)
    final_kernel<<<1, 64>>>(out);                           // 7
}

// round 3
// speedup vs baseline: 1.3279x; 1.0677x over previous
#include <cuda_runtime.h>
#include <math.h>

// Problem geometry
#define C_    80
#define H_    128
#define W_    256
#define HW_   32768          // H_*W_
#define CHW_  2621440        // C_*HW_
#define D_    256
#define P_    131072         // 256*512 embedding spatial
#define KTOP  50
#define NBINS 2048
#define CAP   65536
#define SORTN 4096
#define GEMM_BLOCKS 512      // P_ / 256 cols per block
#define OUT_SCORES 6553600   // KTOP * P_
#define OUT_CATS   6553650

// ---------------- scratch (static device globals; no allocation) -------------
__device__ float g_masked[CHW_];
__device__ int   g_hist[NBINS];      // zero-init at load; self-zeroed per replay
__device__ int   g_thresh_bin;
__device__ int   g_cand_cnt;         // reset by select_kernel each replay
__device__ float g_cand_val[CAP];
__device__ int   g_cand_idx[CAP];
__device__ float g_scores[KTOP];
__device__ int   g_spatial[KTOP];
__device__ int   g_cats[KTOP];
__device__ float g_AT[D_ * KTOP];            // A^T: [d][k]
__device__ float g_psum[GEMM_BLOCKS * KTOP];
__device__ float g_pcnt[GEMM_BLOCKS * KTOP];

__device__ __forceinline__ float fast_sigmoid(float x) {
    return 1.0f / (1.0f + __expf(-x));
}

// packed f32x2 helpers (sm_100+)
__device__ __forceinline__ unsigned long long pk2(float x, float y) {
    unsigned long long r;
    asm("mov.b64 %0, {%1, %2};" : "=l"(r) : "f"(x), "f"(y));
    return r;
}
__device__ __forceinline__ unsigned long long fma2(unsigned long long a,
                                                   unsigned long long b,
                                                   unsigned long long c) {
    unsigned long long d;
    asm("fma.rn.f32x2 %0, %1, %2, %3;" : "=l"(d) : "l"(a), "l"(b), "l"(c));
    return d;
}
__device__ __forceinline__ void upk2(unsigned long long v, float& x, float& y) {
    asm("mov.b64 {%0, %1}, %2;" : "=f"(x), "=f"(y) : "l"(v));
}

// ---------------- 1: fused sigmoid + avg3 + max3 + peak mask + histogram -----
// grid (8, 80): blockIdx.y = class, blockIdx.x = row-block of 16 rows.
#define SW 260
__global__ void __launch_bounds__(256) fused_detect(const float* __restrict__ x) {
    __shared__ float s_sig[20 * SW];
    __shared__ float s_cent[18 * SW];
    __shared__ int   s_hist[NBINS];

    int c   = blockIdx.y;
    int r0  = blockIdx.x * 16;
    int tid = threadIdx.x;

    for (int i = tid; i < NBINS; i += 256) s_hist[i] = 0;

    const float* base = x + c * HW_;

    // phase 1: sigmoid into smem (zero padding outside image)
    for (int i = tid; i < 20 * 256; i += 256) {
        int row = i >> 8;
        int col = i & 255;
        int gr  = r0 - 2 + row;
        float v = 0.0f;
        if (gr >= 0 && gr < H_) v = fast_sigmoid(base[gr * W_ + col]);
        s_sig[row * SW + col + 1] = v;
        if (col == 0)   s_sig[row * SW + 0]   = 0.0f;
        if (col == 255) s_sig[row * SW + 257] = 0.0f;
    }
    __syncthreads();

    // phase 2: centers = 0.5*(sig + avg3x3(sig)) for rows [r0-1, r0+17)
    for (int i = tid; i < 18 * 256; i += 256) {
        int rj  = i >> 8;
        int col = i & 255;
        int gr  = r0 - 1 + rj;
        float v = 0.0f;
        if (gr >= 0 && gr < H_) {
            float sum = 0.0f;
            #pragma unroll
            for (int dr = 0; dr < 3; dr++) {
                const float* p = s_sig + (rj + dr) * SW + col;
                sum += p[0] + p[1] + p[2];
            }
            float center = s_sig[(rj + 1) * SW + col + 1];
            v = 0.5f * (center + sum * (1.0f / 9.0f));
        }
        s_cent[rj * SW + col + 1] = v;
        if (col == 0)   s_cent[rj * SW + 0]   = 0.0f;
        if (col == 255) s_cent[rj * SW + 257] = 0.0f;
    }
    __syncthreads();

    // phase 3: 3x3 max, peak mask, masked value out + histogram
    for (int i = tid; i < 16 * 256; i += 256) {
        int ri  = i >> 8;
        int col = i & 255;
        float m = 0.0f;
        #pragma unroll
        for (int dr = 0; dr < 3; dr++) {
            const float* p = s_cent + (ri + dr) * SW + col;
            m = fmaxf(m, fmaxf(p[0], fmaxf(p[1], p[2])));
        }
        float cv = s_cent[(ri + 1) * SW + col + 1];
        float v  = (m == cv) ? cv : 0.0f;
        g_masked[c * HW_ + (r0 + ri) * W_ + col] = v;
        int bin = (int)(v * (float)NBINS);
        bin = bin < 0 ? 0 : (bin > NBINS - 1 ? NBINS - 1 : bin);
        atomicAdd(&s_hist[bin], 1);
    }
    __syncthreads();
    for (int i = tid; i < NBINS; i += 256)
        if (s_hist[i]) atomicAdd(&g_hist[i], s_hist[i]);
}

// ---------------- 2: threshold bin via suffix-sum; self-zero hist ------------
__global__ void thresh_kernel() {
    __shared__ int a[NBINS], b[NBINS];
    int t = threadIdx.x;   // 1024
    for (int i = t; i < NBINS; i += 1024) a[i] = g_hist[i];
    __syncthreads();
    int* src = a; int* dst = b;
    for (int off = 1; off < NBINS; off <<= 1) {
        for (int i = t; i < NBINS; i += 1024)
            dst[i] = src[i] + ((i + off < NBINS) ? src[i + off] : 0);
        __syncthreads();
        int* tmp = src; src = dst; dst = tmp;
    }
    // src[i] = count of values with bin >= i
    for (int i = t; i < NBINS; i += 1024) {
        if (i >= 1 && src[i] >= KTOP && (i == NBINS - 1 || src[i + 1] < KTOP))
            g_thresh_bin = i;
    }
    if (t == 0 && src[1] < KTOP) g_thresh_bin = 1;
    for (int i = t; i < NBINS; i += 1024) g_hist[i] = 0;
}

// ---------------- 3: collect candidates --------------------------------------
__global__ void collect_kernel() {
    int i = blockIdx.x * blockDim.x + threadIdx.x;
    if (i >= CHW_) return;
    float v = g_masked[i];
    int tb = g_thresh_bin;
    if (tb < 1) tb = 1;
    int bin = (int)(v * (float)NBINS);
    bin = bin < 0 ? 0 : (bin > NBINS - 1 ? NBINS - 1 : bin);
    if (bin >= tb && v > 0.0f) {
        int pos = atomicAdd(&g_cand_cnt, 1);
        if (pos < CAP) { g_cand_val[pos] = v; g_cand_idx[pos] = i; }
    }
}

// ---------------- 4: top-50 via one bitonic sort of packed u64 keys ----------
// key = (float_bits(v) << 32) | ~idx  -> descending sort == (v desc, idx asc)
__global__ void __launch_bounds__(512) select_kernel() {
    __shared__ unsigned long long s[SORTN];
    int t = threadIdx.x;
    int n = g_cand_cnt;
    if (n > SORTN) n = SORTN;

    for (int i = t; i < SORTN; i += 512) {
        unsigned long long key = 0ull;
        if (i < n) {
            unsigned int vb = __float_as_uint(g_cand_val[i]);
            unsigned int ix = ~(unsigned int)g_cand_idx[i];
            key = ((unsigned long long)vb << 32) | ix;
        }
        s[i] = key;
    }
    __syncthreads();

    // bitonic sort, descending
    for (int k = 2; k <= SORTN; k <<= 1) {
        for (int j = k >> 1; j > 0; j >>= 1) {
            for (int i = t; i < SORTN; i += 512) {
                int ixj = i ^ j;
                if (ixj > i) {
                    bool desc = ((i & k) == 0);
                    unsigned long long a = s[i], b = s[ixj];
                    bool sw = desc ? (a < b) : (a > b);
                    if (sw) { s[i] = b; s[ixj] = a; }
                }
            }
            __syncthreads();
        }
    }

    if (t < KTOP) {
        unsigned long long key = s[t];
        unsigned int vb = (unsigned int)(key >> 32);
        if (vb != 0u) {
            unsigned int idx = ~(unsigned int)(key & 0xffffffffull);
            g_scores[t]  = __uint_as_float(vb);
            g_cats[t]    = (int)(idx >> 15);          // / HW_
            g_spatial[t] = (int)(idx & (HW_ - 1));    // % HW_
        } else {
            g_scores[t] = 0.0f; g_cats[t] = 0; g_spatial[t] = 0;
        }
    }
    if (t == 0) g_cand_cnt = 0;   // reset for next replay
}

// ---------------- 5: gather kernels A^T[d][k] (one block per k) --------------
__global__ void gather_kernel(const float* __restrict__ ks) {
    int k  = blockIdx.x;
    int sp = g_spatial[k];
    for (int d = threadIdx.x; d < D_; d += 256)
        g_AT[d * KTOP + k] = ks[d * HW_ + sp];
}

// ---------------- 6: GEMM [50,256]x[256,131072] + sigmoid + rescore ---------
__global__ void __launch_bounds__(128) gemm_kernel(const float* __restrict__ emb,
                                                   float* __restrict__ out) {
    extern __shared__ float smem[];
    float* As   = smem;              // 12800 floats: [d][k]
    float* redS = smem + 12800;      // [4][50]
    float* redC = redS + 200;        // [4][50]

    int tid = threadIdx.x;
    for (int i = tid; i < D_ * KTOP; i += 128) As[i] = g_AT[i];
    __syncthreads();

    const unsigned long long* As64 = (const unsigned long long*)As; // [d][kk]

    int c0 = blockIdx.x * 256 + tid * 2;
    const float2* ep = (const float2*)(emb + c0);   // stride per d: P_/2 float2

    unsigned long long acc0[25], acc1[25];
    #pragma unroll
    for (int kk = 0; kk < 25; kk++) { acc0[kk] = 0ull; acc1[kk] = 0ull; }

    float2 eb[4];
    #pragma unroll
    for (int j = 0; j < 4; j++) eb[j] = __ldg(&ep[j * (P_ / 2)]);

    for (int d0 = 0; d0 < D_; d0 += 4) {
        float2 nb[4];
        #pragma unroll
        for (int j = 0; j < 4; j++) {
            int dn = d0 + 4 + j;
            if (dn > D_ - 1) dn = D_ - 1;
            nb[j] = __ldg(&ep[dn * (P_ / 2)]);
        }
        #pragma unroll
        for (int j = 0; j < 4; j++) {
            int d = d0 + j;
            unsigned long long e0 = pk2(eb[j].x, eb[j].x);
            unsigned long long e1 = pk2(eb[j].y, eb[j].y);
            const unsigned long long* a = As64 + d * 25;
            #pragma unroll
            for (int kk = 0; kk < 25; kk++) {
                unsigned long long av = a[kk];
                acc0[kk] = fma2(av, e0, acc0[kk]);
                acc1[kk] = fma2(av, e1, acc1[kk]);
            }
        }
        #pragma unroll
        for (int j = 0; j < 4; j++) eb[j] = nb[j];
    }

    // epilogue: sigmoid, store masks, warp-reduce rescore partials
    int lane = tid & 31, warp = tid >> 5;
    #pragma unroll
    for (int kk = 0; kk < 25; kk++) {
        float a, b, c, d;
        upk2(acc0[kk], a, c);   // a: k=2kk col0, c: k=2kk+1 col0
        upk2(acc1[kk], b, d);   // b: k=2kk col1, d: k=2kk+1 col1

        {
            float m0 = fast_sigmoid(a), m1 = fast_sigmoid(b);
            float2 st; st.x = m0; st.y = m1;
            *(float2*)(out + (2 * kk) * P_ + c0) = st;
            float s  = (m0 > 0.4f ? m0 : 0.0f) + (m1 > 0.4f ? m1 : 0.0f);
            float cn = (m0 > 0.4f ? 1.0f : 0.0f) + (m1 > 0.4f ? 1.0f : 0.0f);
            #pragma unroll
            for (int o = 16; o > 0; o >>= 1) {
                s  += __shfl_down_sync(0xffffffffu, s,  o);
                cn += __shfl_down_sync(0xffffffffu, cn, o);
            }
            if (lane == 0) { redS[warp * KTOP + 2 * kk] = s; redC[warp * KTOP + 2 * kk] = cn; }
        }
        {
            float m0 = fast_sigmoid(c), m1 = fast_sigmoid(d);
            float2 st; st.x = m0; st.y = m1;
            *(float2*)(out + (2 * kk + 1) * P_ + c0) = st;
            float s  = (m0 > 0.4f ? m0 : 0.0f) + (m1 > 0.4f ? m1 : 0.0f);
            float cn = (m0 > 0.4f ? 1.0f : 0.0f) + (m1 > 0.4f ? 1.0f : 0.0f);
            #pragma unroll
            for (int o = 16; o > 0; o >>= 1) {
                s  += __shfl_down_sync(0xffffffffu, s,  o);
                cn += __shfl_down_sync(0xffffffffu, cn, o);
            }
            if (lane == 0) { redS[warp * KTOP + 2 * kk + 1] = s; redC[warp * KTOP + 2 * kk + 1] = cn; }
        }
    }
    __syncthreads();
    if (tid < KTOP) {
        float s  = redS[tid] + redS[KTOP + tid] + redS[2 * KTOP + tid] + redS[3 * KTOP + tid];
        float cn = redC[tid] + redC[KTOP + tid] + redC[2 * KTOP + tid] + redC[3 * KTOP + tid];
        g_psum[blockIdx.x * KTOP + tid] = s;
        g_pcnt[blockIdx.x * KTOP + tid] = cn;
    }
}

// ---------------- 7: final scores/cats ---------------------------------------
__global__ void final_kernel(float* __restrict__ out) {
    int k = threadIdx.x;
    if (k >= KTOP) return;
    float s = 0.0f, cn = 0.0f;
    for (int b = 0; b < GEMM_BLOCKS; b++) {
        s  += g_psum[b * KTOP + k];
        cn += g_pcnt[b * KTOP + k];
    }
    float factor = s / fmaxf(cn, 1e-8f);
    float sc = g_scores[k];
    float valid = (sc > 0.1f) ? 1.0f : 0.0f;
    out[OUT_SCORES + k] = sc * factor * valid;
    out[OUT_CATS + k]   = (float)g_cats[k];
}

// ---------------- launch -----------------------------------------------------
extern "C" void kernel_launch(void* const* d_in, const int* in_sizes, int n_in,
                              void* d_out, int out_size) {
    const float* thing_map    = (const float*)d_in[0];
    const float* kernel_space = (const float*)d_in[1];
    const float* embeddings   = (const float*)d_in[2];
    float* out = (float*)d_out;

    static bool attr_set = false;
    if (!attr_set) {
        cudaFuncSetAttribute(gemm_kernel,
                             cudaFuncAttributeMaxDynamicSharedMemorySize, 53248);
        attr_set = true;
    }

    fused_detect<<<dim3(8, 80), 256>>>(thing_map);             // 1
    thresh_kernel<<<1, 1024>>>();                              // 2
    collect_kernel<<<(CHW_ + 255) / 256, 256>>>();             // 3
    select_kernel<<<1, 512>>>();                               // 4
    gather_kernel<<<KTOP, 256>>>(kernel_space);                // 5
    gemm_kernel<<<GEMM_BLOCKS, 128, 53248>>>(embeddings, out); // 6
    final_kernel<<<1, 64>>>(out);                              // 7
}

// round 4
// speedup vs baseline: 1.8151x; 1.3670x over previous
#include <cuda_runtime.h>
#include <math.h>

// Problem geometry
#define C_    80
#define H_    128
#define W_    256
#define HW_   32768          // H_*W_
#define CHW_  2621440        // C_*HW_
#define D_    256
#define P_    131072         // 256*512 embedding spatial
#define KTOP  50
#define NBINS 2048
#define CAP   65536
#define SELN  4096
#define GEMM_BLOCKS 512      // 256 col-blocks x 2 row-halves
#define OUT_SCORES 6553600   // KTOP * P_
#define OUT_CATS   6553650

typedef unsigned long long u64;

// ---------------- scratch (static device globals; no allocation) -------------
__device__ float g_masked[CHW_];
__device__ int   g_hist[NBINS];      // zero-init at load; self-zeroed per replay
__device__ int   g_thresh_bin;
__device__ int   g_cand_cnt;         // reset by select_kernel each replay
__device__ float g_cand_val[CAP];
__device__ int   g_cand_idx[CAP];
__device__ float g_scores[KTOP];
__device__ int   g_spatial[KTOP];
__device__ int   g_cats[KTOP];
__device__ u64   g_A2[2 * D_ * 13];          // [half][d][13] k-pair-packed A
__device__ float g_psum[GEMM_BLOCKS * 25];
__device__ float g_pcnt[GEMM_BLOCKS * 25];

__device__ __forceinline__ float fast_sigmoid(float x) {
    return 1.0f / (1.0f + __expf(-x));
}

// packed f32x2 helpers (sm_100+)
__device__ __forceinline__ u64 pk2(float x, float y) {
    u64 r;
    asm("mov.b64 %0, {%1, %2};" : "=l"(r) : "f"(x), "f"(y));
    return r;
}
__device__ __forceinline__ u64 fma2(u64 a, u64 b, u64 c) {
    u64 d;
    asm("fma.rn.f32x2 %0, %1, %2, %3;" : "=l"(d) : "l"(a), "l"(b), "l"(c));
    return d;
}
__device__ __forceinline__ void upk2(u64 v, float& x, float& y) {
    asm("mov.b64 {%0, %1}, %2;" : "=f"(x), "=f"(y) : "l"(v));
}

// ---------------- 1: fused sigmoid + avg3 + max3 + peak mask + histogram -----
#define SW 260
__global__ void __launch_bounds__(256) fused_detect(const float* __restrict__ x) {
    __shared__ float s_sig[20 * SW];
    __shared__ float s_cent[18 * SW];
    __shared__ int   s_hist[NBINS];

    int c   = blockIdx.y;
    int r0  = blockIdx.x * 16;
    int tid = threadIdx.x;

    for (int i = tid; i < NBINS; i += 256) s_hist[i] = 0;

    const float* base = x + c * HW_;

    for (int i = tid; i < 20 * 256; i += 256) {
        int row = i >> 8;
        int col = i & 255;
        int gr  = r0 - 2 + row;
        float v = 0.0f;
        if (gr >= 0 && gr < H_) v = fast_sigmoid(base[gr * W_ + col]);
        s_sig[row * SW + col + 1] = v;
        if (col == 0)   s_sig[row * SW + 0]   = 0.0f;
        if (col == 255) s_sig[row * SW + 257] = 0.0f;
    }
    __syncthreads();

    for (int i = tid; i < 18 * 256; i += 256) {
        int rj  = i >> 8;
        int col = i & 255;
        int gr  = r0 - 1 + rj;
        float v = 0.0f;
        if (gr >= 0 && gr < H_) {
            float sum = 0.0f;
            #pragma unroll
            for (int dr = 0; dr < 3; dr++) {
                const float* p = s_sig + (rj + dr) * SW + col;
                sum += p[0] + p[1] + p[2];
            }
            float center = s_sig[(rj + 1) * SW + col + 1];
            v = 0.5f * (center + sum * (1.0f / 9.0f));
        }
        s_cent[rj * SW + col + 1] = v;
        if (col == 0)   s_cent[rj * SW + 0]   = 0.0f;
        if (col == 255) s_cent[rj * SW + 257] = 0.0f;
    }
    __syncthreads();

    for (int i = tid; i < 16 * 256; i += 256) {
        int ri  = i >> 8;
        int col = i & 255;
        float m = 0.0f;
        #pragma unroll
        for (int dr = 0; dr < 3; dr++) {
            const float* p = s_cent + (ri + dr) * SW + col;
            m = fmaxf(m, fmaxf(p[0], fmaxf(p[1], p[2])));
        }
        float cv = s_cent[(ri + 1) * SW + col + 1];
        float v  = (m == cv) ? cv : 0.0f;
        g_masked[c * HW_ + (r0 + ri) * W_ + col] = v;
        int bin = (int)(v * (float)NBINS);
        bin = bin < 0 ? 0 : (bin > NBINS - 1 ? NBINS - 1 : bin);
        atomicAdd(&s_hist[bin], 1);
    }
    __syncthreads();
    for (int i = tid; i < NBINS; i += 256)
        if (s_hist[i]) atomicAdd(&g_hist[i], s_hist[i]);
}

// ---------------- 2: threshold bin via suffix-sum; self-zero hist ------------
__global__ void thresh_kernel() {
    __shared__ int a[NBINS], b[NBINS];
    int t = threadIdx.x;   // 1024
    for (int i = t; i < NBINS; i += 1024) a[i] = g_hist[i];
    __syncthreads();
    int* src = a; int* dst = b;
    for (int off = 1; off < NBINS; off <<= 1) {
        for (int i = t; i < NBINS; i += 1024)
            dst[i] = src[i] + ((i + off < NBINS) ? src[i + off] : 0);
        __syncthreads();
        int* tmp = src; src = dst; dst = tmp;
    }
    for (int i = t; i < NBINS; i += 1024) {
        if (i >= 1 && src[i] >= KTOP && (i == NBINS - 1 || src[i + 1] < KTOP))
            g_thresh_bin = i;
    }
    if (t == 0 && src[1] < KTOP) g_thresh_bin = 1;
    for (int i = t; i < NBINS; i += 1024) g_hist[i] = 0;
}

// ---------------- 3: collect candidates --------------------------------------
__global__ void collect_kernel() {
    int i = blockIdx.x * blockDim.x + threadIdx.x;
    if (i >= CHW_) return;
    float v = g_masked[i];
    int tb = g_thresh_bin;
    if (tb < 1) tb = 1;
    int bin = (int)(v * (float)NBINS);
    bin = bin < 0 ? 0 : (bin > NBINS - 1 ? NBINS - 1 : bin);
    if (bin >= tb && v > 0.0f) {
        int pos = atomicAdd(&g_cand_cnt, 1);
        if (pos < CAP) { g_cand_val[pos] = v; g_cand_idx[pos] = i; }
    }
}

// ---------------- 4: top-50 via exact rank (distinct u64 keys) ---------------
// key = (float_bits(v) << 32) | ~idx ; rank_i = #{j : key_j > key_i}
__global__ void __launch_bounds__(1024) select_kernel() {
    __shared__ u64 keys[SELN];
    int t = threadIdx.x;
    int n = g_cand_cnt;
    if (n > SELN) n = SELN;

    // defaults (in case n < KTOP)
    if (t < KTOP) { g_scores[t] = 0.0f; g_cats[t] = 0; g_spatial[t] = 0; }

    for (int i = t; i < n; i += 1024) {
        unsigned int vb = __float_as_uint(g_cand_val[i]);
        unsigned int ix = ~(unsigned int)g_cand_idx[i];
        keys[i] = ((u64)vb << 32) | ix;
    }
    __syncthreads();

    for (int i = t; i < n; i += 1024) {
        u64 ki = keys[i];
        int rank = 0;
        for (int j = 0; j < n; j++) rank += (keys[j] > ki);
        if (rank < KTOP) {
            unsigned int vb  = (unsigned int)(ki >> 32);
            unsigned int idx = ~(unsigned int)(ki & 0xffffffffull);
            g_scores[rank]  = __uint_as_float(vb);
            g_cats[rank]    = (int)(idx >> 15);          // / HW_
            g_spatial[rank] = (int)(idx & (HW_ - 1));    // % HW_
        }
    }
    if (t == 0) g_cand_cnt = 0;   // reset for next replay
}

// ---------------- 5: gather A into [half][d][13] k-pair-packed u64 -----------
// grid KTOP blocks x 256 threads; block k writes its float slot of each pair.
__global__ void gather_kernel(const float* __restrict__ ks) {
    int k    = blockIdx.x;
    int sp   = g_spatial[k];
    int half = k / 25;
    int lr   = k % 25;
    int p    = lr >> 1;
    int slot = lr & 1;
    float* A2f = (float*)g_A2;
    int d = threadIdx.x;   // 256 threads == D_
    float v = ks[d * HW_ + sp];
    int base = (half * D_ * 13 + d * 13 + p) * 2;
    A2f[base + slot] = v;
    if (lr == 24) A2f[base + 1] = 0.0f;   // pad slot of last (odd) pair
}

// ---------------- 6: GEMM [25,256]x[256,512cols/block] + sigmoid + rescore ---
// grid 512: colblk = bx>>1 (512 cols each), half = bx&1 (25 rows each).
// Thread: 4 columns x 25 rows; A k-pair packed; e via one float4/d.
__global__ void __launch_bounds__(128, 3) gemm_kernel(const float* __restrict__ emb,
                                                      float* __restrict__ out) {
    __shared__ u64   As[D_ * 13];
    __shared__ float redS[4 * 25];
    __shared__ float redC[4 * 25];

    int tid    = threadIdx.x;
    int half   = blockIdx.x & 1;
    int colblk = blockIdx.x >> 1;

    const u64* src = g_A2 + half * D_ * 13;
    for (int i = tid; i < D_ * 13; i += 128) As[i] = src[i];
    __syncthreads();

    int c0 = colblk * 512 + tid * 4;
    const float4* ep = (const float4*)(emb + c0);    // stride P_/4 per d

    u64 acc[13][4];
    #pragma unroll
    for (int p = 0; p < 13; p++)
        #pragma unroll
        for (int c = 0; c < 4; c++) acc[p][c] = 0ull;

    float4 cur = __ldg(&ep[0]);
    for (int d = 0; d < D_; d++) {
        float4 nxt = (d < D_ - 1) ? __ldg(&ep[(d + 1) * (P_ / 4)]) : cur;
        u64 e0 = pk2(cur.x, cur.x);
        u64 e1 = pk2(cur.y, cur.y);
        u64 e2 = pk2(cur.z, cur.z);
        u64 e3 = pk2(cur.w, cur.w);
        const u64* a = As + d * 13;
        #pragma unroll
        for (int p = 0; p < 13; p++) {
            u64 av = a[p];
            acc[p][0] = fma2(av, e0, acc[p][0]);
            acc[p][1] = fma2(av, e1, acc[p][1]);
            acc[p][2] = fma2(av, e2, acc[p][2]);
            acc[p][3] = fma2(av, e3, acc[p][3]);
        }
        cur = nxt;
    }

    // epilogue: rows 0..24 (global row = half*25 + lr), lr = 2p+slot
    int lane = tid & 31, warp = tid >> 5;
    int rbase = half * 25;
    #pragma unroll
    for (int p = 0; p < 13; p++) {
        float lo[4], hi[4];
        #pragma unroll
        for (int c = 0; c < 4; c++) upk2(acc[p][c], lo[c], hi[c]);

        // row lr = 2p (always valid)
        {
            float4 st;
            float m0 = fast_sigmoid(lo[0]), m1 = fast_sigmoid(lo[1]);
            float m2 = fast_sigmoid(lo[2]), m3 = fast_sigmoid(lo[3]);
            st.x = m0; st.y = m1; st.z = m2; st.w = m3;
            *(float4*)(out + (rbase + 2 * p) * P_ + c0) = st;
            float s  = (m0 > 0.4f ? m0 : 0.0f) + (m1 > 0.4f ? m1 : 0.0f)
                     + (m2 > 0.4f ? m2 : 0.0f) + (m3 > 0.4f ? m3 : 0.0f);
            float cn = (m0 > 0.4f ? 1.0f : 0.0f) + (m1 > 0.4f ? 1.0f : 0.0f)
                     + (m2 > 0.4f ? 1.0f : 0.0f) + (m3 > 0.4f ? 1.0f : 0.0f);
            #pragma unroll
            for (int o = 16; o > 0; o >>= 1) {
                s  += __shfl_down_sync(0xffffffffu, s,  o);
                cn += __shfl_down_sync(0xffffffffu, cn, o);
            }
            if (lane == 0) { redS[warp * 25 + 2 * p] = s; redC[warp * 25 + 2 * p] = cn; }
        }
        // row lr = 2p+1 (skip pad at p == 12)
        if (p < 12) {
            float4 st;
            float m0 = fast_sigmoid(hi[0]), m1 = fast_sigmoid(hi[1]);
            float m2 = fast_sigmoid(hi[2]), m3 = fast_sigmoid(hi[3]);
            st.x = m0; st.y = m1; st.z = m2; st.w = m3;
            *(float4*)(out + (rbase + 2 * p + 1) * P_ + c0) = st;
            float s  = (m0 > 0.4f ? m0 : 0.0f) + (m1 > 0.4f ? m1 : 0.0f)
                     + (m2 > 0.4f ? m2 : 0.0f) + (m3 > 0.4f ? m3 : 0.0f);
            float cn = (m0 > 0.4f ? 1.0f : 0.0f) + (m1 > 0.4f ? 1.0f : 0.0f)
                     + (m2 > 0.4f ? 1.0f : 0.0f) + (m3 > 0.4f ? 1.0f : 0.0f);
            #pragma unroll
            for (int o = 16; o > 0; o >>= 1) {
                s  += __shfl_down_sync(0xffffffffu, s,  o);
                cn += __shfl_down_sync(0xffffffffu, cn, o);
            }
            if (lane == 0) { redS[warp * 25 + 2 * p + 1] = s; redC[warp * 25 + 2 * p + 1] = cn; }
        }
    }
    __syncthreads();
    if (tid < 25) {
        float s  = redS[tid] + redS[25 + tid] + redS[50 + tid] + redS[75 + tid];
        float cn = redC[tid] + redC[25 + tid] + redC[50 + tid] + redC[75 + tid];
        g_psum[blockIdx.x * 25 + tid] = s;
        g_pcnt[blockIdx.x * 25 + tid] = cn;
    }
}

// ---------------- 7: final scores/cats ---------------------------------------
__global__ void final_kernel(float* __restrict__ out) {
    int k = threadIdx.x;
    if (k >= KTOP) return;
    int half = k / 25;
    int lr   = k % 25;
    float s = 0.0f, cn = 0.0f;
    for (int cb = 0; cb < 256; cb++) {
        int b = cb * 2 + half;
        s  += g_psum[b * 25 + lr];
        cn += g_pcnt[b * 25 + lr];
    }
    float factor = s / fmaxf(cn, 1e-8f);
    float sc = g_scores[k];
    float valid = (sc > 0.1f) ? 1.0f : 0.0f;
    out[OUT_SCORES + k] = sc * factor * valid;
    out[OUT_CATS + k]   = (float)g_cats[k];
}

// ---------------- launch -----------------------------------------------------
extern "C" void kernel_launch(void* const* d_in, const int* in_sizes, int n_in,
                              void* d_out, int out_size) {
    const float* thing_map    = (const float*)d_in[0];
    const float* kernel_space = (const float*)d_in[1];
    const float* embeddings   = (const float*)d_in[2];
    float* out = (float*)d_out;

    fused_detect<<<dim3(8, 80), 256>>>(thing_map);             // 1
    thresh_kernel<<<1, 1024>>>();                              // 2
    collect_kernel<<<(CHW_ + 255) / 256, 256>>>();             // 3
    select_kernel<<<1, 1024>>>();                              // 4
    gather_kernel<<<KTOP, 256>>>(kernel_space);                // 5
    gemm_kernel<<<GEMM_BLOCKS, 128>>>(embeddings, out);        // 6
    final_kernel<<<1, 64>>>(out);                              // 7
}